// round 7
// baseline (speedup 1.0000x reference)
#include <cuda_runtime.h>

#define TW 64            // output tile width
#define TH 32            // output tile height
#define IR (TH + 10)     // 42 intermediate (horizontally-convolved) rows
#define IW (TW + 10)     // 74 staged input cols
#define ISTR 75          // input tile row stride (odd -> conflict-free)
#define HS 65            // intermediate buffer row stride (odd)
#define WDIM 512
#define HDIM 512
#define GRIDX (WDIM / TW)                 // 8
#define GRIDY (HDIM / TH)                 // 16
#define NBLOCKS (GRIDX * GRIDY * 48)      // 6144
#define SMEM_FLOATS (2 * IR * ISTR + 5 * IR * HS)
#define SMEM_BYTES (SMEM_FLOATS * 4)      // 79920 B -> needs dynamic smem opt-in

// Normalized 1-D Gaussian, sigma=1.5, 11 taps. All accesses at compile-time
// indices after unroll -> ptxas folds taps into FFMA-imm (rt_SMSP=1).
__device__ constexpr float GW[11] = {
    0.00102838f, 0.00759875f, 0.03600077f, 0.10936125f, 0.21300531f,
    0.26601172f,
    0.21300531f, 0.10936125f, 0.03600077f, 0.00759875f, 0.00102838f};

__device__ float g_partials[NBLOCKS];
__device__ unsigned g_counter = 0;

__global__ __launch_bounds__(256, 2) void ssim_main(
    const float* __restrict__ pred, const float* __restrict__ targ,
    float* __restrict__ out) {
  extern __shared__ float smem[];
  float* sp = smem;                       // [IR * ISTR]
  float* st = smem + IR * ISTR;           // [IR * ISTR]
  float* hb = smem + 2 * IR * ISTR;       // [5][IR * HS]
  __shared__ float red[8];
  __shared__ double dred[8];
  __shared__ unsigned is_last;

  const int tid = threadIdx.x;
  const int gx0 = blockIdx.x * TW - 5;
  const int gy0 = blockIdx.y * TH - 5;
  const size_t plane_off = (size_t)blockIdx.z * (WDIM * HDIM);
  const float* __restrict__ pbase = pred + plane_off;
  const float* __restrict__ tbase = targ + plane_off;

  // ---- Stage A: stage input tiles with zero halo (SAME zero padding) ----
  for (int i = tid; i < IR * IW; i += 256) {
    int r = i / IW;
    int c = i - r * IW;
    int gy = gy0 + r, gx = gx0 + c;
    float pv = 0.f, tv = 0.f;
    if ((unsigned)gy < (unsigned)HDIM && (unsigned)gx < (unsigned)WDIM) {
      int idx = gy * WDIM + gx;
      pv = pbase[idx];
      tv = tbase[idx];
    }
    sp[r * ISTR + c] = pv;
    st[r * ISTR + c] = tv;
  }
  __syncthreads();

  // ---- Stage B: horizontal conv of {p, t, p^2, t^2, p*t} ----
  // 252 tasks (one per thread, single trip): 42 rows x 6 col-groups
  // (widths 11,11,11,11,10,10 covering output cols 0..63).
  if (tid < IR * 6) {
    const int row = tid / 6;
    const int g = tid - row * 6;
    const int gw11 = (g < 4);                    // group width 11 else 10
    const int cb = (g < 5) ? g * 11 : 54;
    const float* __restrict__ pr = &sp[row * ISTR + cb];
    const float* __restrict__ tr = &st[row * ISTR + cb];
    float hp[11], ht[11], hpp[11], htt[11], hpt[11];
#pragma unroll
    for (int j = 0; j < 11; ++j) {
      hp[j] = 0.f; ht[j] = 0.f; hpp[j] = 0.f; htt[j] = 0.f; hpt[j] = 0.f;
    }
#pragma unroll
    for (int k = 0; k < 21; ++k) {
      // k=20 only feeds j=10, which is only stored when gw11; the staged
      // read at cb+20 is always in-bounds of the padded row (ISTR=75).
      float p = pr[k], t = tr[k];
      float pp = p * p, tt = t * t, pt = p * t;
#pragma unroll
      for (int j = 0; j < 11; ++j) {
        const int tap = k - j;
        if (tap >= 0 && tap <= 10) {
          const float w = GW[tap];
          hp[j] += w * p;
          ht[j] += w * t;
          hpp[j] += w * pp;
          htt[j] += w * tt;
          hpt[j] += w * pt;
        }
      }
    }
    const int ob = row * HS + cb;
#pragma unroll
    for (int j = 0; j < 11; ++j) {
      if (j < 10 || gw11) {
        hb[0 * IR * HS + ob + j] = hp[j];
        hb[1 * IR * HS + ob + j] = ht[j];
        hb[2 * IR * HS + ob + j] = hpp[j];
        hb[3 * IR * HS + ob + j] = htt[j];
        hb[4 * IR * HS + ob + j] = hpt[j];
      }
    }
  }
  __syncthreads();

  // ---- Stage C: vertical conv + fused SSIM epilogue ----
  // thread -> (col = tid%64, chunk of 8 consecutive output rows)
  const int col = tid & 63;
  const int rb = (tid >> 6) * 8;  // 0,8,16,24
  float acc[8][5];
#pragma unroll
  for (int j = 0; j < 8; ++j)
#pragma unroll
    for (int ch = 0; ch < 5; ++ch) acc[j][ch] = 0.f;

#pragma unroll
  for (int ir = 0; ir < 18; ++ir) {
    const int o = (rb + ir) * HS + col;
    const float v0 = hb[0 * IR * HS + o];
    const float v1 = hb[1 * IR * HS + o];
    const float v2 = hb[2 * IR * HS + o];
    const float v3 = hb[3 * IR * HS + o];
    const float v4 = hb[4 * IR * HS + o];
#pragma unroll
    for (int j = 0; j < 8; ++j) {
      const int tap = ir - j;
      if (tap >= 0 && tap <= 10) {
        const float w = GW[tap];
        acc[j][0] += w * v0;
        acc[j][1] += w * v1;
        acc[j][2] += w * v2;
        acc[j][3] += w * v3;
        acc[j][4] += w * v4;
      }
    }
  }

  float lsum = 0.f;
#pragma unroll
  for (int j = 0; j < 8; ++j) {
    const float mp = acc[j][0];
    const float mt = acc[j][1];
    const float mp2 = mp * mp;
    const float mt2 = mt * mt;
    const float mct = mp * mt;
    const float sgp = acc[j][2] - mp2;
    const float sgt = acc[j][3] - mt2;
    const float sgc = acc[j][4] - mct;
    const float num = (2.0f * mct + 1e-4f) * (2.0f * sgc + 9e-4f);
    const float den = (mp2 + mt2 + 1e-4f) * (sgp + sgt + 9e-4f);
    lsum += __fdividef(num, den);
  }

  // ---- fixed-order block reduction (deterministic) ----
#pragma unroll
  for (int o = 16; o > 0; o >>= 1)
    lsum += __shfl_down_sync(0xffffffffu, lsum, o);
  if ((tid & 31) == 0) red[tid >> 5] = lsum;
  __syncthreads();

  if (tid == 0) {
    float v = 0.f;
#pragma unroll
    for (int i = 0; i < 8; ++i) v += red[i];
    const int bid =
        (blockIdx.z * gridDim.y + blockIdx.y) * gridDim.x + blockIdx.x;
    g_partials[bid] = v;
    __threadfence();
    unsigned prev = atomicAdd(&g_counter, 1u);
    is_last = (prev == (unsigned)(NBLOCKS - 1)) ? 1u : 0u;
  }
  __syncthreads();

  // ---- last CTA: fixed-order global reduction, write scalar output ----
  if (is_last) {
    __threadfence();  // acquire: make all partials visible
    double s = 0.0;
    for (int i = tid; i < NBLOCKS; i += 256) s += (double)g_partials[i];
#pragma unroll
    for (int o = 16; o > 0; o >>= 1) s += __shfl_down_sync(0xffffffffu, s, o);
    if ((tid & 31) == 0) dred[tid >> 5] = s;
    __syncthreads();
    if (tid == 0) {
      double t = 0.0;
#pragma unroll
      for (int i = 0; i < 8; ++i) t += dred[i];
      out[0] = (float)(1.0 - t / 12582912.0);  // 16*3*512*512
      g_counter = 0;  // reset for next graph replay
    }
  }
}

extern "C" void kernel_launch(void* const* d_in, const int* in_sizes, int n_in,
                              void* d_out, int out_size) {
  (void)in_sizes; (void)n_in; (void)out_size;
  const float* pred = (const float*)d_in[0];
  const float* targ = (const float*)d_in[1];
  // 79.9 KB dynamic smem needs the opt-in (idempotent; host-side, capture-safe)
  cudaFuncSetAttribute(ssim_main, cudaFuncAttributeMaxDynamicSharedMemorySize,
                       SMEM_BYTES);
  dim3 grid(GRIDX, GRIDY, 48);
  ssim_main<<<grid, 256, SMEM_BYTES>>>(pred, targ, (float*)d_out);
}